// round 1
// baseline (speedup 1.0000x reference)
#include <cuda_runtime.h>
#include <math.h>

#define BB 4096
#define SS 128
#define DD 64
#define HH 256
#define INF 8192
#define H4 1024

// ---------------- scratch (device globals; zero-init at load) ----------------
__device__ float g_scale[INF];
__device__ float g_shift[INF];
__device__ float g_xn[(size_t)BB * INF];      // 128 MB
__device__ float g_proj[(size_t)BB * INF];    // 128 MB
__device__ float g_gates[(size_t)BB * H4];    // 16 MB
__device__ float g_c[(size_t)BB * HH];        // 4 MB
__device__ float g_h0[(size_t)BB * HH];       // never written -> stays zero
__device__ float g_hs[(size_t)BB * SS * HH];  // 512 MB
__device__ float g_logits[(size_t)BB * SS];   // 2 MB
__device__ float g_beta[(size_t)BB * SS];     // 2 MB

// ---------------- BatchNorm: per-feature stats -> scale/shift ----------------
__global__ void bn_stats(const float* __restrict__ x,
                         const float* __restrict__ gamma,
                         const float* __restrict__ beta) {
    int k = blockIdx.x * blockDim.x + threadIdx.x;  // feature index
    float s = 0.f, s2 = 0.f;
    #pragma unroll 8
    for (int b = 0; b < BB; b++) {
        float v = x[(size_t)b * INF + k];
        s += v; s2 += v * v;
    }
    float mean = s * (1.f / BB);
    float var  = s2 * (1.f / BB) - mean * mean;
    float rs   = rsqrtf(var + 1e-5f);
    float sc   = gamma[k] * rs;
    g_scale[k] = sc;
    g_shift[k] = beta[k] - mean * sc;
}

__global__ void bn_apply(const float* __restrict__ x, float* __restrict__ xn) {
    size_t i = (size_t)blockIdx.x * blockDim.x + threadIdx.x;  // float4 index
    float4 v = ((const float4*)x)[i];
    int k = (int)((i * 4) & (INF - 1));
    float4 o;
    o.x = fmaf(v.x, g_scale[k + 0], g_shift[k + 0]);
    o.y = fmaf(v.y, g_scale[k + 1], g_shift[k + 1]);
    o.z = fmaf(v.z, g_scale[k + 2], g_shift[k + 2]);
    o.w = fmaf(v.w, g_scale[k + 3], g_shift[k + 3]);
    ((float4*)xn)[i] = o;
}

// ---------------- generic C = A @ B^T (+bias, optional relu) ----------------
// A: [M,K] row-major (lda), B: [N,K] row-major (ldb). All dims divide tiles.
template <int BM, int BN, int BK, int TM, int TN>
__global__ void __launch_bounds__((BM / TM) * (BN / TN))
gemm_abt(const float* __restrict__ A, int lda,
         const float* __restrict__ Bm, int ldb,
         const float* __restrict__ bias, int relu,
         float* __restrict__ C, int ldc, int K) {
    constexpr int NT = (BM / TM) * (BN / TN);
    constexpr int BNT = BN / TN;
    __shared__ __align__(16) float As[BK][BM];
    __shared__ __align__(16) float Bs[BK][BN];
    const int tid = threadIdx.x;
    const int tx = tid % BNT;
    const int ty = tid / BNT;
    const int m0 = blockIdx.y * BM;
    const int n0 = blockIdx.x * BN;

    float acc[TM][TN];
    #pragma unroll
    for (int i = 0; i < TM; i++)
        #pragma unroll
        for (int j = 0; j < TN; j++) acc[i][j] = 0.f;

    for (int k0 = 0; k0 < K; k0 += BK) {
        #pragma unroll
        for (int i = tid * 4; i < BM * BK; i += NT * 4) {
            int r = i / BK, c = i % BK;
            float4 v = *(const float4*)(A + (size_t)(m0 + r) * lda + (k0 + c));
            As[c + 0][r] = v.x; As[c + 1][r] = v.y;
            As[c + 2][r] = v.z; As[c + 3][r] = v.w;
        }
        #pragma unroll
        for (int i = tid * 4; i < BN * BK; i += NT * 4) {
            int r = i / BK, c = i % BK;
            float4 v = *(const float4*)(Bm + (size_t)(n0 + r) * ldb + (k0 + c));
            Bs[c + 0][r] = v.x; Bs[c + 1][r] = v.y;
            Bs[c + 2][r] = v.z; Bs[c + 3][r] = v.w;
        }
        __syncthreads();
        #pragma unroll
        for (int kk = 0; kk < BK; kk++) {
            float a[TM], bvals[TN];
            #pragma unroll
            for (int i = 0; i < TM; i++) a[i] = As[kk][ty * TM + i];
            #pragma unroll
            for (int j = 0; j < TN; j++) bvals[j] = Bs[kk][tx * TN + j];
            #pragma unroll
            for (int i = 0; i < TM; i++)
                #pragma unroll
                for (int j = 0; j < TN; j++)
                    acc[i][j] = fmaf(a[i], bvals[j], acc[i][j]);
        }
        __syncthreads();
    }
    #pragma unroll
    for (int i = 0; i < TM; i++) {
        int m = m0 + ty * TM + i;
        #pragma unroll
        for (int j = 0; j < TN; j++) {
            int n = n0 + tx * TN + j;
            float v = acc[i][j];
            if (bias) v += bias[n];
            if (relu) v = fmaxf(v, 0.f);
            C[(size_t)m * ldc + n] = v;
        }
    }
}

// ---- dual-segment GEMM: C = A1@B1^T + A2@B2^T + bias1 + bias2 (LSTM gates) ----
template <int BM, int BN, int BK, int TM, int TN>
__global__ void __launch_bounds__((BM / TM) * (BN / TN))
gemm_dual_abt(const float* __restrict__ A1, int lda1,
              const float* __restrict__ B1, int ldb1, int K1,
              const float* __restrict__ A2, int lda2,
              const float* __restrict__ B2, int ldb2, int K2,
              const float* __restrict__ bias1, const float* __restrict__ bias2,
              float* __restrict__ C, int ldc) {
    constexpr int NT = (BM / TM) * (BN / TN);
    constexpr int BNT = BN / TN;
    __shared__ __align__(16) float As[BK][BM];
    __shared__ __align__(16) float Bs[BK][BN];
    const int tid = threadIdx.x;
    const int tx = tid % BNT;
    const int ty = tid / BNT;
    const int m0 = blockIdx.y * BM;
    const int n0 = blockIdx.x * BN;

    float acc[TM][TN];
    #pragma unroll
    for (int i = 0; i < TM; i++)
        #pragma unroll
        for (int j = 0; j < TN; j++) acc[i][j] = 0.f;

    #pragma unroll 1
    for (int phase = 0; phase < 2; phase++) {
        const float* A = phase ? A2 : A1;
        const float* Bm = phase ? B2 : B1;
        const int lda = phase ? lda2 : lda1;
        const int ldb = phase ? ldb2 : ldb1;
        const int K = phase ? K2 : K1;
        for (int k0 = 0; k0 < K; k0 += BK) {
            #pragma unroll
            for (int i = tid * 4; i < BM * BK; i += NT * 4) {
                int r = i / BK, c = i % BK;
                float4 v = *(const float4*)(A + (size_t)(m0 + r) * lda + (k0 + c));
                As[c + 0][r] = v.x; As[c + 1][r] = v.y;
                As[c + 2][r] = v.z; As[c + 3][r] = v.w;
            }
            #pragma unroll
            for (int i = tid * 4; i < BN * BK; i += NT * 4) {
                int r = i / BK, c = i % BK;
                float4 v = *(const float4*)(Bm + (size_t)(n0 + r) * ldb + (k0 + c));
                Bs[c + 0][r] = v.x; Bs[c + 1][r] = v.y;
                Bs[c + 2][r] = v.z; Bs[c + 3][r] = v.w;
            }
            __syncthreads();
            #pragma unroll
            for (int kk = 0; kk < BK; kk++) {
                float a[TM], bvals[TN];
                #pragma unroll
                for (int i = 0; i < TM; i++) a[i] = As[kk][ty * TM + i];
                #pragma unroll
                for (int j = 0; j < TN; j++) bvals[j] = Bs[kk][tx * TN + j];
                #pragma unroll
                for (int i = 0; i < TM; i++)
                    #pragma unroll
                    for (int j = 0; j < TN; j++)
                        acc[i][j] = fmaf(a[i], bvals[j], acc[i][j]);
            }
            __syncthreads();
        }
    }
    #pragma unroll
    for (int i = 0; i < TM; i++) {
        int m = m0 + ty * TM + i;
        #pragma unroll
        for (int j = 0; j < TN; j++) {
            int n = n0 + tx * TN + j;
            C[(size_t)m * ldc + n] = acc[i][j] + bias1[n] + bias2[n];
        }
    }
}

// ---------------- LSTM elementwise cell ----------------
__device__ __forceinline__ float sigf(float x) { return 1.f / (1.f + expf(-x)); }

__global__ void lstm_cell(int s) {
    int idx = blockIdx.x * blockDim.x + threadIdx.x;  // over B*H
    int b = idx >> 8;
    int h = idx & 255;
    const float* g = g_gates + (size_t)b * H4;
    float ig = sigf(g[h]);
    float fg = sigf(g[HH + h]);
    float gg = tanhf(g[2 * HH + h]);
    float og = sigf(g[3 * HH + h]);
    float cp = (s == 0) ? 0.f : g_c[idx];
    float cn = fmaf(fg, cp, ig * gg);
    g_c[idx] = cn;
    g_hs[((size_t)b * SS + s) * HH + h] = og * tanhf(cn);
}

// ---------------- softmax over S=128 (input already relu'd) ----------------
__global__ void softmax_rows() {
    int b = blockIdx.x;
    int t = threadIdx.x;  // 128 threads
    __shared__ float sh[4];
    float v = g_logits[(size_t)b * SS + t];
    float m = v;
    #pragma unroll
    for (int o = 16; o > 0; o >>= 1) m = fmaxf(m, __shfl_xor_sync(0xffffffffu, m, o));
    if ((t & 31) == 0) sh[t >> 5] = m;
    __syncthreads();
    float m4 = fmaxf(fmaxf(sh[0], sh[1]), fmaxf(sh[2], sh[3]));
    float e = expf(v - m4);
    float ssum = e;
    #pragma unroll
    for (int o = 16; o > 0; o >>= 1) ssum += __shfl_xor_sync(0xffffffffu, ssum, o);
    __syncthreads();
    if ((t & 31) == 0) sh[t >> 5] = ssum;
    __syncthreads();
    float tot = sh[0] + sh[1] + sh[2] + sh[3];
    g_beta[(size_t)b * SS + t] = e / tot;
}

// ---------------- pooled = sum_s beta*hs ; out = pooled @ W_out^T ----------------
__global__ void pool_out(const float* __restrict__ W_out, float* __restrict__ out) {
    int b = blockIdx.x;
    int t = threadIdx.x;  // 256 threads, t == h
    __shared__ float sb[SS];
    __shared__ float red[8];
    if (t < SS) sb[t] = g_beta[(size_t)b * SS + t];
    __syncthreads();
    const float* hrow = g_hs + (size_t)b * SS * HH + t;
    float acc = 0.f;
    #pragma unroll 4
    for (int s = 0; s < SS; s++) acc = fmaf(hrow[(size_t)s * HH], sb[s], acc);
    float v = acc * W_out[t];
    #pragma unroll
    for (int o = 16; o > 0; o >>= 1) v += __shfl_xor_sync(0xffffffffu, v, o);
    if ((t & 31) == 0) red[t >> 5] = v;
    __syncthreads();
    if (t == 0) {
        float r = 0.f;
        #pragma unroll
        for (int w = 0; w < 8; w++) r += red[w];
        out[b] = r;
    }
}

// ---------------- launch ----------------
extern "C" void kernel_launch(void* const* d_in, const int* in_sizes, int n_in,
                              void* d_out, int out_size) {
    const float* x     = (const float*)d_in[0];
    const float* gamma = (const float*)d_in[1];
    const float* beta  = (const float*)d_in[2];
    const float* W_in  = (const float*)d_in[3];
    const float* W_ih  = (const float*)d_in[4];
    const float* b_ih  = (const float*)d_in[5];
    const float* W_hh  = (const float*)d_in[6];
    const float* b_hh  = (const float*)d_in[7];
    const float* W_ta  = (const float*)d_in[8];
    const float* b_ta  = (const float*)d_in[9];
    const float* W_out = (const float*)d_in[10];
    float* out = (float*)d_out;

    float *p_xn, *p_proj, *p_hs, *p_h0, *p_gates, *p_logits;
    cudaGetSymbolAddress((void**)&p_xn, g_xn);
    cudaGetSymbolAddress((void**)&p_proj, g_proj);
    cudaGetSymbolAddress((void**)&p_hs, g_hs);
    cudaGetSymbolAddress((void**)&p_h0, g_h0);
    cudaGetSymbolAddress((void**)&p_gates, g_gates);
    cudaGetSymbolAddress((void**)&p_logits, g_logits);

    // 1. BatchNorm
    bn_stats<<<INF / 256, 256>>>(x, gamma, beta);
    bn_apply<<<(BB * INF / 4) / 256, 256>>>(x, p_xn);

    // 2. proj = xn @ W_in^T   [4096 x 8192], K=8192
    gemm_abt<128, 128, 8, 8, 8><<<dim3(INF / 128, BB / 128), 256>>>(
        p_xn, INF, W_in, INF, nullptr, 0, p_proj, INF, INF);

    // 3. LSTM scan: gates = xs_s @ W_ih^T + h_{s-1} @ W_hh^T + b_ih + b_hh
    for (int s = 0; s < SS; s++) {
        const float* hprev = (s == 0) ? p_h0 : (p_hs + (size_t)(s - 1) * HH);
        int ldah = (s == 0) ? HH : SS * HH;
        gemm_dual_abt<128, 128, 8, 8, 8><<<dim3(H4 / 128, BB / 128), 256>>>(
            p_proj + (size_t)s * DD, INF, W_ih, DD, DD,
            hprev, ldah, W_hh, HH, HH,
            b_ih, b_hh, p_gates, H4);
        lstm_cell<<<BB * HH / 256, 256>>>(s);
    }

    // 4. attention logits = relu(hs_flat @ W_ta^T + b_ta)   [4096 x 128], K=32768
    gemm_abt<32, 128, 8, 2, 8><<<dim3(1, BB / 32), 256>>>(
        p_hs, SS * HH, W_ta, SS * HH, b_ta, 1, p_logits, SS, SS * HH);

    // 5. softmax over S, then pooled @ W_out^T
    softmax_rows<<<BB, SS>>>();
    pool_out<<<BB, HH>>>(W_out, out);
}

// round 3
// speedup vs baseline: 1.7201x; 1.7201x over previous
#include <cuda_runtime.h>
#include <cuda_bf16.h>
#include <math.h>
#include <stdint.h>

#define BB 4096
#define SS 128
#define DD 64
#define HH 256
#define INF 8192
#define H4 1024
#define KSPLIT 16
#define KCH ((SS * HH) / KSPLIT)   // 2048

// ---------------- scratch (device globals; zero-init at load) ----------------
__device__ float g_scale[INF];
__device__ float g_shift[INF];
__device__ __nv_bfloat16 g_xnh[(size_t)BB * INF];   // 64 MB
__device__ __nv_bfloat16 g_xnl[(size_t)BB * INF];   // 64 MB
__device__ __nv_bfloat16 g_wh[(size_t)INF * INF];   // 128 MB
__device__ __nv_bfloat16 g_wl[(size_t)INF * INF];   // 128 MB
__device__ float g_proj[(size_t)BB * INF];          // 128 MB
__device__ float g_gx[(size_t)BB * SS * H4];        // 2 GB
__device__ float g_c[(size_t)BB * HH];              // 4 MB
__device__ float g_h0[(size_t)BB * HH];             // stays zero
__device__ float g_hs[(size_t)BB * SS * HH];        // 512 MB
__device__ float g_pattn[(size_t)KSPLIT * BB * SS]; // 32 MB
__device__ float g_beta[(size_t)BB * SS];           // 2 MB

// ============================ PTX helpers (family-wide only) ============================
__device__ __forceinline__ uint32_t smem_to_u32(const void* p) {
    uint32_t a;
    asm("{ .reg .u64 t; cvta.to.shared.u64 t, %1; cvt.u32.u64 %0, t; }" : "=r"(a) : "l"(p));
    return a;
}

__device__ __forceinline__ void ldsm_x4(uint32_t* r, uint32_t a) {
    asm volatile("ldmatrix.sync.aligned.m8n8.x4.shared.b16 {%0,%1,%2,%3}, [%4];"
                 : "=r"(r[0]), "=r"(r[1]), "=r"(r[2]), "=r"(r[3]) : "r"(a));
}
__device__ __forceinline__ void ldsm_x2(uint32_t* r, uint32_t a) {
    asm volatile("ldmatrix.sync.aligned.m8n8.x2.shared.b16 {%0,%1}, [%2];"
                 : "=r"(r[0]), "=r"(r[1]) : "r"(a));
}
__device__ __forceinline__ void mma16816(float* c, const uint32_t* a, const uint32_t* b) {
    asm volatile(
        "mma.sync.aligned.m16n8k16.row.col.f32.bf16.bf16.f32 "
        "{%0,%1,%2,%3}, {%4,%5,%6,%7}, {%8,%9}, {%0,%1,%2,%3};"
        : "+f"(c[0]), "+f"(c[1]), "+f"(c[2]), "+f"(c[3])
        : "r"(a[0]), "r"(a[1]), "r"(a[2]), "r"(a[3]), "r"(b[0]), "r"(b[1]));
}

// ---------------- BatchNorm stats -> scale/shift ----------------
__global__ void bn_stats(const float* __restrict__ x,
                         const float* __restrict__ gamma,
                         const float* __restrict__ beta) {
    int k = blockIdx.x * blockDim.x + threadIdx.x;
    float s = 0.f, s2 = 0.f;
    #pragma unroll 8
    for (int b = 0; b < BB; b++) {
        float v = x[(size_t)b * INF + k];
        s += v; s2 += v * v;
    }
    float mean = s * (1.f / BB);
    float var = s2 * (1.f / BB) - mean * mean;
    float sc = gamma[k] * rsqrtf(var + 1e-5f);
    g_scale[k] = sc;
    g_shift[k] = beta[k] - mean * sc;
}

// BN apply fused with bf16 hi/lo split
__global__ void bn_apply_split(const float* __restrict__ x) {
    size_t i = (size_t)blockIdx.x * blockDim.x + threadIdx.x;  // float4 index
    float4 v = ((const float4*)x)[i];
    int k = (int)((i * 4) & (INF - 1));
    float o0 = fmaf(v.x, g_scale[k + 0], g_shift[k + 0]);
    float o1 = fmaf(v.y, g_scale[k + 1], g_shift[k + 1]);
    float o2 = fmaf(v.z, g_scale[k + 2], g_shift[k + 2]);
    float o3 = fmaf(v.w, g_scale[k + 3], g_shift[k + 3]);
    __nv_bfloat16 h0 = __float2bfloat16(o0), h1 = __float2bfloat16(o1);
    __nv_bfloat16 h2 = __float2bfloat16(o2), h3 = __float2bfloat16(o3);
    __nv_bfloat162 ph0; ph0.x = h0; ph0.y = h1;
    __nv_bfloat162 ph1; ph1.x = h2; ph1.y = h3;
    *(__nv_bfloat162*)(g_xnh + i * 4) = ph0;
    *(__nv_bfloat162*)(g_xnh + i * 4 + 2) = ph1;
    __nv_bfloat162 pl0, pl1;
    pl0.x = __float2bfloat16(o0 - __bfloat162float(h0));
    pl0.y = __float2bfloat16(o1 - __bfloat162float(h1));
    pl1.x = __float2bfloat16(o2 - __bfloat162float(h2));
    pl1.y = __float2bfloat16(o3 - __bfloat162float(h3));
    *(__nv_bfloat162*)(g_xnl + i * 4) = pl0;
    *(__nv_bfloat162*)(g_xnl + i * 4 + 2) = pl1;
}

// W_in -> hi/lo bf16
__global__ void cvt_w(const float* __restrict__ w) {
    size_t i = (size_t)blockIdx.x * blockDim.x + threadIdx.x;  // float4 index
    float4 v = ((const float4*)w)[i];
    __nv_bfloat16 h0 = __float2bfloat16(v.x), h1 = __float2bfloat16(v.y);
    __nv_bfloat16 h2 = __float2bfloat16(v.z), h3 = __float2bfloat16(v.w);
    __nv_bfloat162 ph0; ph0.x = h0; ph0.y = h1;
    __nv_bfloat162 ph1; ph1.x = h2; ph1.y = h3;
    *(__nv_bfloat162*)(g_wh + i * 4) = ph0;
    *(__nv_bfloat162*)(g_wh + i * 4 + 2) = ph1;
    __nv_bfloat162 pl0, pl1;
    pl0.x = __float2bfloat16(v.x - __bfloat162float(h0));
    pl0.y = __float2bfloat16(v.y - __bfloat162float(h1));
    pl1.x = __float2bfloat16(v.z - __bfloat162float(h2));
    pl1.y = __float2bfloat16(v.w - __bfloat162float(h3));
    *(__nv_bfloat162*)(g_wl + i * 4) = pl0;
    *(__nv_bfloat162*)(g_wl + i * 4 + 2) = pl1;
}

// ============ proj = xn @ W_in^T via mma.sync bf16x3 (fp32-accurate) ============
// CTA 128x128, BK=32 bf16, 8 warps (2M x 4N), warp tile 64x32, double-buffered.
// smem rows padded to 40 bf16 (80B) -> conflict-free ldmatrix.
#define TPAD 40
#define TILE_B (128 * TPAD * 2)          // 10240 bytes per tile
#define STAGE_B (4 * TILE_B)             // 40960 bytes per stage

__global__ void __launch_bounds__(256, 1)
proj_mma(float* __restrict__ C) {
    extern __shared__ __align__(128) char sm[];
    const int tid = threadIdx.x;
    const int wid = tid >> 5, lane = tid & 31;
    const int m0 = blockIdx.x * 128;
    const int n0 = blockIdx.y * 128;
    const int wm = (wid >> 2) * 64;
    const int wn = (wid & 3) * 32;
    const uint32_t smu = smem_to_u32(sm);

    const __nv_bfloat16* src0 = g_xnh + (size_t)m0 * INF;
    const __nv_bfloat16* src1 = g_xnl + (size_t)m0 * INF;
    const __nv_bfloat16* src2 = g_wh + (size_t)n0 * INF;
    const __nv_bfloat16* src3 = g_wl + (size_t)n0 * INF;

    float acc[4][4][4];
    #pragma unroll
    for (int i = 0; i < 4; i++)
        #pragma unroll
        for (int j = 0; j < 4; j++)
            #pragma unroll
            for (int f = 0; f < 4; f++) acc[i][j][f] = 0.f;

    // gmem staging: per stage each thread loads 2 float4 per tile
    float4 stg[4][2];
    const int r0 = tid >> 2, g0 = tid & 3;          // idx = tid
    const int r1 = (tid + 256) >> 2, g1 = tid & 3;  // idx = tid + 256

    auto ldg = [&](int k0) {
        const __nv_bfloat16* s[4] = {src0, src1, src2, src3};
        #pragma unroll
        for (int t = 0; t < 4; t++) {
            stg[t][0] = *(const float4*)(s[t] + (size_t)r0 * INF + k0 + g0 * 8);
            stg[t][1] = *(const float4*)(s[t] + (size_t)r1 * INF + k0 + g1 * 8);
        }
    };
    auto sts = [&](int stage) {
        char* base = sm + stage * STAGE_B;
        #pragma unroll
        for (int t = 0; t < 4; t++) {
            *(float4*)(base + t * TILE_B + r0 * 80 + g0 * 16) = stg[t][0];
            *(float4*)(base + t * TILE_B + r1 * 80 + g1 * 16) = stg[t][1];
        }
    };
    auto compute = [&](int stage) {
        const uint32_t sAh = smu + stage * STAGE_B;
        const uint32_t sAl = sAh + TILE_B;
        const uint32_t sBh = sAh + 2 * TILE_B;
        const uint32_t sBl = sAh + 3 * TILE_B;
        #pragma unroll
        for (int ks = 0; ks < 2; ks++) {
            const int kb = ks * 32;  // byte offset within row (16 bf16)
            uint32_t bh[4][2], bl[4][2];
            const uint32_t boff = (uint32_t)(wn + (lane & 7)) * 80 + kb + ((lane >> 3) & 1) * 16;
            #pragma unroll
            for (int ni = 0; ni < 4; ni++) {
                ldsm_x2(bh[ni], sBh + boff + ni * 8 * 80);
                ldsm_x2(bl[ni], sBl + boff + ni * 8 * 80);
            }
            const uint32_t aoff = (uint32_t)(wm + (lane & 15)) * 80 + kb + (lane >> 4) * 16;
            #pragma unroll
            for (int mi = 0; mi < 4; mi++) {
                uint32_t ah[4], al[4];
                ldsm_x4(ah, sAh + aoff + mi * 16 * 80);
                ldsm_x4(al, sAl + aoff + mi * 16 * 80);
                #pragma unroll
                for (int ni = 0; ni < 4; ni++) {
                    mma16816(acc[mi][ni], ah, bh[ni]);
                    mma16816(acc[mi][ni], ah, bl[ni]);
                    mma16816(acc[mi][ni], al, bh[ni]);
                }
            }
        }
    };

    ldg(0); sts(0);
    __syncthreads();
    int cur = 0;
    #pragma unroll 1
    for (int k0 = 0; k0 < INF; k0 += 32) {
        bool more = (k0 + 32 < INF);
        if (more) ldg(k0 + 32);
        compute(cur);
        if (more) sts(cur ^ 1);
        __syncthreads();
        cur ^= 1;
    }

    const int gid = lane >> 2, tig = lane & 3;
    #pragma unroll
    for (int mi = 0; mi < 4; mi++) {
        int row0 = m0 + wm + mi * 16 + gid;
        #pragma unroll
        for (int ni = 0; ni < 4; ni++) {
            int col = n0 + wn + ni * 8 + tig * 2;
            float2 v0; v0.x = acc[mi][ni][0]; v0.y = acc[mi][ni][1];
            float2 v1; v1.x = acc[mi][ni][2]; v1.y = acc[mi][ni][3];
            *(float2*)(C + (size_t)row0 * INF + col) = v0;
            *(float2*)(C + (size_t)(row0 + 8) * INF + col) = v1;
        }
    }
}

// ============ double-buffered fp32 GEMM: C = A@B^T (+bias1+bias2, relu) ============
__global__ void __launch_bounds__(256, 2)
gemm_abt_db(const float* __restrict__ A, int lda,
            const float* __restrict__ B, int ldb, int K,
            const float* __restrict__ bias1, const float* __restrict__ bias2, int relu,
            float* __restrict__ C, int ldc, int kza, long long czc) {
    A += (size_t)blockIdx.z * kza;
    B += (size_t)blockIdx.z * kza;
    C += (size_t)blockIdx.z * czc;
    __shared__ __align__(16) float As[2][16][128];
    __shared__ __align__(16) float Bs[2][16][128];
    const int tid = threadIdx.x;
    const int tx = tid & 15;
    const int ty = tid >> 4;
    const int m0 = blockIdx.y * 128;
    const int n0 = blockIdx.x * 128;

    float acc[8][8];
    #pragma unroll
    for (int i = 0; i < 8; i++)
        #pragma unroll
        for (int j = 0; j < 8; j++) acc[i][j] = 0.f;

    float4 ra[2], rb[2];
    auto ld = [&](int k0) {
        #pragma unroll
        for (int u = 0; u < 2; ++u) {
            int i = (tid + u * 256) << 2;
            int r = i >> 4, cc = i & 15;
            ra[u] = *(const float4*)(A + (size_t)(m0 + r) * lda + k0 + cc);
            rb[u] = *(const float4*)(B + (size_t)(n0 + r) * ldb + k0 + cc);
        }
    };
    auto st = [&](int buf) {
        #pragma unroll
        for (int u = 0; u < 2; ++u) {
            int i = (tid + u * 256) << 2;
            int r = i >> 4, cc = i & 15;
            As[buf][cc][r] = ra[u].x; As[buf][cc + 1][r] = ra[u].y;
            As[buf][cc + 2][r] = ra[u].z; As[buf][cc + 3][r] = ra[u].w;
            Bs[buf][cc][r] = rb[u].x; Bs[buf][cc + 1][r] = rb[u].y;
            Bs[buf][cc + 2][r] = rb[u].z; Bs[buf][cc + 3][r] = rb[u].w;
        }
    };

    ld(0); st(0);
    __syncthreads();
    int cur = 0;
    #pragma unroll 1
    for (int k0 = 0; k0 < K; k0 += 16) {
        bool more = (k0 + 16 < K);
        if (more) ld(k0 + 16);
        #pragma unroll
        for (int kk = 0; kk < 16; ++kk) {
            float a[8], b[8];
            *(float4*)(a) = *(const float4*)&As[cur][kk][ty * 8];
            *(float4*)(a + 4) = *(const float4*)&As[cur][kk][ty * 8 + 4];
            *(float4*)(b) = *(const float4*)&Bs[cur][kk][tx * 8];
            *(float4*)(b + 4) = *(const float4*)&Bs[cur][kk][tx * 8 + 4];
            #pragma unroll
            for (int i = 0; i < 8; i++)
                #pragma unroll
                for (int j = 0; j < 8; j++)
                    acc[i][j] = fmaf(a[i], b[j], acc[i][j]);
        }
        if (more) st(cur ^ 1);
        __syncthreads();
        cur ^= 1;
    }
    #pragma unroll
    for (int i = 0; i < 8; i++) {
        int m = m0 + ty * 8 + i;
        #pragma unroll
        for (int j = 0; j < 8; j++) {
            int n = n0 + tx * 8 + j;
            float v = acc[i][j];
            if (bias1) v += bias1[n];
            if (bias2) v += bias2[n];
            if (relu) v = fmaxf(v, 0.f);
            C[(size_t)m * ldc + n] = v;
        }
    }
}

// ============ LSTM step: gates = hprev@W_hh^T + gx ; fused cell epilogue ============
__device__ __forceinline__ float sigf(float x) { return 1.f / (1.f + expf(-x)); }

__global__ void __launch_bounds__(256, 2)
lstm_step(const float* __restrict__ hprev, int ldah, const float* __restrict__ Whh, int s) {
    __shared__ __align__(16) float As[2][16][128];
    __shared__ __align__(16) float Bs[2][16][128];
    const int tid = threadIdx.x;
    const int tx = tid & 15;
    const int ty = tid >> 4;
    const int m0 = blockIdx.y * 128;
    const int h0 = blockIdx.x * 32;

    float acc[8][8];
    #pragma unroll
    for (int i = 0; i < 8; i++)
        #pragma unroll
        for (int j = 0; j < 8; j++) acc[i][j] = 0.f;

    float4 ra[2], rb[2];
    auto ld = [&](int k0) {
        #pragma unroll
        for (int u = 0; u < 2; ++u) {
            int i = (tid + u * 256) << 2;
            int r = i >> 4, cc = i & 15;
            ra[u] = *(const float4*)(hprev + (size_t)(m0 + r) * ldah + k0 + cc);
            int row = (r & 3) * HH + h0 + (r >> 2);
            rb[u] = *(const float4*)(Whh + (size_t)row * HH + k0 + cc);
        }
    };
    auto st = [&](int buf) {
        #pragma unroll
        for (int u = 0; u < 2; ++u) {
            int i = (tid + u * 256) << 2;
            int r = i >> 4, cc = i & 15;
            As[buf][cc][r] = ra[u].x; As[buf][cc + 1][r] = ra[u].y;
            As[buf][cc + 2][r] = ra[u].z; As[buf][cc + 3][r] = ra[u].w;
            Bs[buf][cc][r] = rb[u].x; Bs[buf][cc + 1][r] = rb[u].y;
            Bs[buf][cc + 2][r] = rb[u].z; Bs[buf][cc + 3][r] = rb[u].w;
        }
    };

    ld(0); st(0);
    __syncthreads();
    int cur = 0;
    #pragma unroll 1
    for (int k0 = 0; k0 < HH; k0 += 16) {
        bool more = (k0 + 16 < HH);
        if (more) ld(k0 + 16);
        #pragma unroll
        for (int kk = 0; kk < 16; ++kk) {
            float a[8], b[8];
            *(float4*)(a) = *(const float4*)&As[cur][kk][ty * 8];
            *(float4*)(a + 4) = *(const float4*)&As[cur][kk][ty * 8 + 4];
            *(float4*)(b) = *(const float4*)&Bs[cur][kk][tx * 8];
            *(float4*)(b + 4) = *(const float4*)&Bs[cur][kk][tx * 8 + 4];
            #pragma unroll
            for (int i = 0; i < 8; i++)
                #pragma unroll
                for (int j = 0; j < 8; j++)
                    acc[i][j] = fmaf(a[i], b[j], acc[i][j]);
        }
        if (more) st(cur ^ 1);
        __syncthreads();
        cur ^= 1;
    }

    // fused LSTM cell epilogue: logical col j -> (h = h0 + j/4, gate = j&3)
    #pragma unroll
    for (int i = 0; i < 8; i++) {
        int b = m0 + ty * 8 + i;
        const float* gxp = g_gx + ((size_t)b * SS + s) * H4;
        #pragma unroll
        for (int hl = 0; hl < 2; hl++) {
            int h = h0 + tx * 2 + hl;
            float gi = acc[i][hl * 4 + 0] + gxp[0 * HH + h];
            float gf = acc[i][hl * 4 + 1] + gxp[1 * HH + h];
            float gg = acc[i][hl * 4 + 2] + gxp[2 * HH + h];
            float go = acc[i][hl * 4 + 3] + gxp[3 * HH + h];
            float ig = sigf(gi);
            float fg = sigf(gf);
            float gv = tanhf(gg);
            float og = sigf(go);
            float cp = (s == 0) ? 0.f : g_c[(size_t)b * HH + h];
            float cn = fmaf(fg, cp, ig * gv);
            g_c[(size_t)b * HH + h] = cn;
            g_hs[((size_t)b * SS + s) * HH + h] = og * tanhf(cn);
        }
    }
}

// ---------------- attention: reduce split-K partials, relu, softmax ----------------
__global__ void attn_reduce_softmax(const float* __restrict__ b_ta) {
    int b = blockIdx.x;
    int t = threadIdx.x;  // 128
    __shared__ float sh[4];
    float v = 0.f;
    #pragma unroll
    for (int z = 0; z < KSPLIT; z++) v += g_pattn[((size_t)z * BB + b) * SS + t];
    v = fmaxf(v + b_ta[t], 0.f);
    float m = v;
    #pragma unroll
    for (int o = 16; o > 0; o >>= 1) m = fmaxf(m, __shfl_xor_sync(0xffffffffu, m, o));
    if ((t & 31) == 0) sh[t >> 5] = m;
    __syncthreads();
    float m4 = fmaxf(fmaxf(sh[0], sh[1]), fmaxf(sh[2], sh[3]));
    float e = expf(v - m4);
    float ssum = e;
    #pragma unroll
    for (int o = 16; o > 0; o >>= 1) ssum += __shfl_xor_sync(0xffffffffu, ssum, o);
    __syncthreads();
    if ((t & 31) == 0) sh[t >> 5] = ssum;
    __syncthreads();
    float tot = sh[0] + sh[1] + sh[2] + sh[3];
    g_beta[(size_t)b * SS + t] = e / tot;
}

// ---------------- pooled = sum_s beta*hs ; out = pooled @ W_out^T ----------------
__global__ void pool_out(const float* __restrict__ W_out, float* __restrict__ out) {
    int b = blockIdx.x;
    int t = threadIdx.x;  // 256, t == h
    __shared__ float sb[SS];
    __shared__ float red[8];
    if (t < SS) sb[t] = g_beta[(size_t)b * SS + t];
    __syncthreads();
    const float* hrow = g_hs + (size_t)b * SS * HH + t;
    float acc = 0.f;
    #pragma unroll 4
    for (int s = 0; s < SS; s++) acc = fmaf(hrow[(size_t)s * HH], sb[s], acc);
    float v = acc * W_out[t];
    #pragma unroll
    for (int o = 16; o > 0; o >>= 1) v += __shfl_xor_sync(0xffffffffu, v, o);
    if ((t & 31) == 0) red[t >> 5] = v;
    __syncthreads();
    if (t == 0) {
        float r = 0.f;
        #pragma unroll
        for (int w = 0; w < 8; w++) r += red[w];
        out[b] = r;
    }
}

// ---------------- launch ----------------
extern "C" void kernel_launch(void* const* d_in, const int* in_sizes, int n_in,
                              void* d_out, int out_size) {
    const float* x     = (const float*)d_in[0];
    const float* gamma = (const float*)d_in[1];
    const float* beta  = (const float*)d_in[2];
    const float* W_in  = (const float*)d_in[3];
    const float* W_ih  = (const float*)d_in[4];
    const float* b_ih  = (const float*)d_in[5];
    const float* W_hh  = (const float*)d_in[6];
    const float* b_hh  = (const float*)d_in[7];
    const float* W_ta  = (const float*)d_in[8];
    const float* b_ta  = (const float*)d_in[9];
    const float* W_out = (const float*)d_in[10];
    float* out = (float*)d_out;

    float *p_proj, *p_gx, *p_hs, *p_h0, *p_pattn;
    cudaGetSymbolAddress((void**)&p_proj, g_proj);
    cudaGetSymbolAddress((void**)&p_gx, g_gx);
    cudaGetSymbolAddress((void**)&p_hs, g_hs);
    cudaGetSymbolAddress((void**)&p_h0, g_h0);
    cudaGetSymbolAddress((void**)&p_pattn, g_pattn);

    const int SMEM_MMA = 2 * STAGE_B;  // 81920 bytes
    cudaFuncSetAttribute(proj_mma, cudaFuncAttributeMaxDynamicSharedMemorySize, SMEM_MMA);

    // 0-1: BatchNorm (stats, then apply fused with bf16 split)
    bn_stats<<<INF / 256, 256>>>(x, gamma, beta);
    bn_apply_split<<<(BB * INF / 4) / 256, 256>>>(x);
    // 2: W_in -> bf16 hi/lo
    cvt_w<<<(INF * INF / 4) / 256, 256>>>(W_in);
    // 3: proj = xn @ W_in^T  (mma.sync bf16x3)
    proj_mma<<<dim3(BB / 128, INF / 128), 256, SMEM_MMA>>>(p_proj);
    // 4: gx = proj2d @ W_ih^T + b_ih + b_hh   [B*S, 1024], K=64
    gemm_abt_db<<<dim3(H4 / 128, (BB * SS) / 128, 1), 256>>>(
        p_proj, DD, W_ih, DD, DD, b_ih, b_hh, 0, p_gx, H4, 0, 0);
    // 5+: LSTM scan with fused cell
    for (int s = 0; s < SS; s++) {
        const float* hprev = (s == 0) ? p_h0 : (p_hs + (size_t)(s - 1) * HH);
        int ldah = (s == 0) ? HH : SS * HH;
        lstm_step<<<dim3(HH / 32, BB / 128), 256>>>(hprev, ldah, W_hh, s);
    }
    // attention: split-K partials then fused reduce+relu+softmax
    gemm_abt_db<<<dim3(1, BB / 128, KSPLIT), 256>>>(
        p_hs, SS * HH, W_ta, SS * HH, KCH, nullptr, nullptr, 0,
        p_pattn, SS, KCH, (long long)BB * SS);
    attn_reduce_softmax<<<BB, SS>>>(b_ta);
    pool_out<<<BB, HH>>>(W_out, out);
}

// round 6
// speedup vs baseline: 2.3636x; 1.3741x over previous
#include <cuda_runtime.h>
#include <cuda_bf16.h>
#include <math.h>
#include <stdint.h>

#define BB 4096
#define SS 128
#define DD 64
#define HH 256
#define INF 8192
#define H4 1024
#define KSPLIT 16
#define KCH ((SS * HH) / KSPLIT)   // 2048

// ---------------- scratch (device globals; zero-init at load) ----------------
__device__ float g_scale[INF];
__device__ float g_shift[INF];
__device__ __nv_bfloat16 g_xnh[(size_t)BB * INF];        // 64 MB
__device__ __nv_bfloat16 g_xnl[(size_t)BB * INF];        // 64 MB
__device__ __nv_bfloat16 g_wh[(size_t)INF * INF];        // 128 MB
__device__ __nv_bfloat16 g_wl[(size_t)INF * INF];        // 128 MB
__device__ float g_proj[(size_t)BB * INF];               // 128 MB
__device__ float g_gx[(size_t)BB * SS * H4];             // 2 GB
__device__ __nv_bfloat16 g_whhh[(size_t)H4 * HH];        // W_hh hi (512 KB)
__device__ __nv_bfloat16 g_whhl[(size_t)H4 * HH];        // W_hh lo
__device__ float g_gates[(size_t)BB * H4];               // 16 MB
__device__ float g_c[(size_t)BB * HH];                   // 4 MB
__device__ float g_hs[(size_t)BB * SS * HH];             // 512 MB (fp32, attn/pool)
__device__ __nv_bfloat16 g_hsbh[(size_t)BB * SS * HH];   // 256 MB (hi, scan chain)
__device__ __nv_bfloat16 g_hsbl[(size_t)BB * SS * HH];   // 256 MB (lo)
__device__ float g_pattn[(size_t)KSPLIT * BB * SS];      // 32 MB
__device__ float g_beta[(size_t)BB * SS];                // 2 MB

// ============================ PTX helpers (family-wide) ============================
__device__ __forceinline__ uint32_t smem_to_u32(const void* p) {
    uint32_t a;
    asm("{ .reg .u64 t; cvta.to.shared.u64 t, %1; cvt.u32.u64 %0, t; }" : "=r"(a) : "l"(p));
    return a;
}
__device__ __forceinline__ void ldsm_x4(uint32_t* r, uint32_t a) {
    asm volatile("ldmatrix.sync.aligned.m8n8.x4.shared.b16 {%0,%1,%2,%3}, [%4];"
                 : "=r"(r[0]), "=r"(r[1]), "=r"(r[2]), "=r"(r[3]) : "r"(a));
}
__device__ __forceinline__ void ldsm_x2(uint32_t* r, uint32_t a) {
    asm volatile("ldmatrix.sync.aligned.m8n8.x2.shared.b16 {%0,%1}, [%2];"
                 : "=r"(r[0]), "=r"(r[1]) : "r"(a));
}
__device__ __forceinline__ void mma16816(float* c, const uint32_t* a, const uint32_t* b) {
    asm volatile(
        "mma.sync.aligned.m16n8k16.row.col.f32.bf16.bf16.f32 "
        "{%0,%1,%2,%3}, {%4,%5,%6,%7}, {%8,%9}, {%0,%1,%2,%3};"
        : "+f"(c[0]), "+f"(c[1]), "+f"(c[2]), "+f"(c[3])
        : "r"(a[0]), "r"(a[1]), "r"(a[2]), "r"(a[3]), "r"(b[0]), "r"(b[1]));
}

// smem tiling: 4 tiles (Ah, Al, Bh, Bl), 128 rows x 32 bf16 padded to 80 B/row.
#define TILE_B (128 * 80)        // 10240 B
#define STAGE_B (4 * TILE_B)     // 40960 B
#define SMEM_MMA (2 * STAGE_B)   // 81920 B

// ---------------- BatchNorm stats -> scale/shift ----------------
__global__ void bn_stats(const float* __restrict__ x,
                         const float* __restrict__ gamma,
                         const float* __restrict__ beta) {
    int k = blockIdx.x * blockDim.x + threadIdx.x;
    float s = 0.f, s2 = 0.f;
    #pragma unroll 8
    for (int b = 0; b < BB; b++) {
        float v = x[(size_t)b * INF + k];
        s += v; s2 += v * v;
    }
    float mean = s * (1.f / BB);
    float var = s2 * (1.f / BB) - mean * mean;
    float sc = gamma[k] * rsqrtf(var + 1e-5f);
    g_scale[k] = sc;
    g_shift[k] = beta[k] - mean * sc;
}

// BN apply fused with bf16 hi/lo split
__global__ void bn_apply_split(const float* __restrict__ x) {
    size_t i = (size_t)blockIdx.x * blockDim.x + threadIdx.x;  // float4 index
    float4 v = ((const float4*)x)[i];
    int k = (int)((i * 4) & (INF - 1));
    float o0 = fmaf(v.x, g_scale[k + 0], g_shift[k + 0]);
    float o1 = fmaf(v.y, g_scale[k + 1], g_shift[k + 1]);
    float o2 = fmaf(v.z, g_scale[k + 2], g_shift[k + 2]);
    float o3 = fmaf(v.w, g_scale[k + 3], g_shift[k + 3]);
    __nv_bfloat16 h0 = __float2bfloat16(o0), h1 = __float2bfloat16(o1);
    __nv_bfloat16 h2 = __float2bfloat16(o2), h3 = __float2bfloat16(o3);
    __nv_bfloat162 ph0; ph0.x = h0; ph0.y = h1;
    __nv_bfloat162 ph1; ph1.x = h2; ph1.y = h3;
    *(__nv_bfloat162*)(g_xnh + i * 4) = ph0;
    *(__nv_bfloat162*)(g_xnh + i * 4 + 2) = ph1;
    __nv_bfloat162 pl0, pl1;
    pl0.x = __float2bfloat16(o0 - __bfloat162float(h0));
    pl0.y = __float2bfloat16(o1 - __bfloat162float(h1));
    pl1.x = __float2bfloat16(o2 - __bfloat162float(h2));
    pl1.y = __float2bfloat16(o3 - __bfloat162float(h3));
    *(__nv_bfloat162*)(g_xnl + i * 4) = pl0;
    *(__nv_bfloat162*)(g_xnl + i * 4 + 2) = pl1;
}

// generic fp32 -> bf16 hi/lo split
__global__ void cvt_split(const float* __restrict__ src,
                          __nv_bfloat16* __restrict__ dh,
                          __nv_bfloat16* __restrict__ dl) {
    size_t i = (size_t)blockIdx.x * blockDim.x + threadIdx.x;  // float4 index
    float4 v = ((const float4*)src)[i];
    __nv_bfloat16 h0 = __float2bfloat16(v.x), h1 = __float2bfloat16(v.y);
    __nv_bfloat16 h2 = __float2bfloat16(v.z), h3 = __float2bfloat16(v.w);
    __nv_bfloat162 ph0; ph0.x = h0; ph0.y = h1;
    __nv_bfloat162 ph1; ph1.x = h2; ph1.y = h3;
    *(__nv_bfloat162*)(dh + i * 4) = ph0;
    *(__nv_bfloat162*)(dh + i * 4 + 2) = ph1;
    __nv_bfloat162 pl0, pl1;
    pl0.x = __float2bfloat16(v.x - __bfloat162float(h0));
    pl0.y = __float2bfloat16(v.y - __bfloat162float(h1));
    pl1.x = __float2bfloat16(v.z - __bfloat162float(h2));
    pl1.y = __float2bfloat16(v.w - __bfloat162float(h3));
    *(__nv_bfloat162*)(dl + i * 4) = pl0;
    *(__nv_bfloat162*)(dl + i * 4 + 2) = pl1;
}

// ============ proj = xn @ W_in^T via mma.sync bf16x3 (fp32 out; R3-verbatim) ============
__global__ void __launch_bounds__(256, 1)
proj_mma(float* __restrict__ C) {
    extern __shared__ __align__(128) char sm[];
    const int tid = threadIdx.x;
    const int wid = tid >> 5, lane = tid & 31;
    const int m0 = blockIdx.x * 128;
    const int n0 = blockIdx.y * 128;
    const int wm = (wid >> 2) * 64;
    const int wn = (wid & 3) * 32;
    const uint32_t smu = smem_to_u32(sm);

    const __nv_bfloat16* src0 = g_xnh + (size_t)m0 * INF;
    const __nv_bfloat16* src1 = g_xnl + (size_t)m0 * INF;
    const __nv_bfloat16* src2 = g_wh + (size_t)n0 * INF;
    const __nv_bfloat16* src3 = g_wl + (size_t)n0 * INF;

    float acc[4][4][4];
    #pragma unroll
    for (int i = 0; i < 4; i++)
        #pragma unroll
        for (int j = 0; j < 4; j++)
            #pragma unroll
            for (int f = 0; f < 4; f++) acc[i][j][f] = 0.f;

    float4 stg[4][2];
    const int r0 = tid >> 2, g0 = tid & 3;
    const int r1 = (tid + 256) >> 2;

    auto ldg = [&](int k0) {
        const __nv_bfloat16* s[4] = {src0, src1, src2, src3};
        #pragma unroll
        for (int t = 0; t < 4; t++) {
            stg[t][0] = *(const float4*)(s[t] + (size_t)r0 * INF + k0 + g0 * 8);
            stg[t][1] = *(const float4*)(s[t] + (size_t)r1 * INF + k0 + g0 * 8);
        }
    };
    auto sts = [&](int stage) {
        char* base = sm + stage * STAGE_B;
        #pragma unroll
        for (int t = 0; t < 4; t++) {
            *(float4*)(base + t * TILE_B + r0 * 80 + g0 * 16) = stg[t][0];
            *(float4*)(base + t * TILE_B + r1 * 80 + g0 * 16) = stg[t][1];
        }
    };
    auto compute = [&](int stage) {
        const uint32_t sAh = smu + stage * STAGE_B;
        const uint32_t sAl = sAh + TILE_B;
        const uint32_t sBh = sAh + 2 * TILE_B;
        const uint32_t sBl = sAh + 3 * TILE_B;
        #pragma unroll
        for (int ks = 0; ks < 2; ks++) {
            const int kb = ks * 32;
            uint32_t bh[4][2], bl[4][2];
            const uint32_t boff = (uint32_t)(wn + (lane & 7)) * 80 + kb + ((lane >> 3) & 1) * 16;
            #pragma unroll
            for (int ni = 0; ni < 4; ni++) {
                ldsm_x2(bh[ni], sBh + boff + ni * 8 * 80);
                ldsm_x2(bl[ni], sBl + boff + ni * 8 * 80);
            }
            const uint32_t aoff = (uint32_t)(wm + (lane & 15)) * 80 + kb + (lane >> 4) * 16;
            #pragma unroll
            for (int mi = 0; mi < 4; mi++) {
                uint32_t ah[4], al[4];
                ldsm_x4(ah, sAh + aoff + mi * 16 * 80);
                ldsm_x4(al, sAl + aoff + mi * 16 * 80);
                #pragma unroll
                for (int ni = 0; ni < 4; ni++) {
                    mma16816(acc[mi][ni], ah, bh[ni]);
                    mma16816(acc[mi][ni], ah, bl[ni]);
                    mma16816(acc[mi][ni], al, bh[ni]);
                }
            }
        }
    };

    ldg(0); sts(0);
    __syncthreads();
    int cur = 0;
    #pragma unroll 1
    for (int k0 = 0; k0 < INF; k0 += 32) {
        bool more = (k0 + 32 < INF);
        if (more) ldg(k0 + 32);
        compute(cur);
        if (more) sts(cur ^ 1);
        __syncthreads();
        cur ^= 1;
    }

    const int gid = lane >> 2, tig = lane & 3;
    #pragma unroll
    for (int mi = 0; mi < 4; mi++) {
        int row0 = m0 + wm + mi * 16 + gid;
        #pragma unroll
        for (int ni = 0; ni < 4; ni++) {
            int col = n0 + wn + ni * 8 + tig * 2;
            float2 v0; v0.x = acc[mi][ni][0]; v0.y = acc[mi][ni][1];
            float2 v1; v1.x = acc[mi][ni][2]; v1.y = acc[mi][ni][3];
            *(float2*)(C + (size_t)row0 * INF + col) = v0;
            *(float2*)(C + (size_t)(row0 + 8) * INF + col) = v1;
        }
    }
}

// ============ hh_mma: g_gates = h_{s-1} @ W_hh^T (bf16x3, proj clone) ============
// A: [4096 x 256] bf16 hi/lo, lda=32768 (hs flat, caller offsets by (s-1)*HH)
// B: g_whhh/g_whhl [1024 x 256], ldb=256. C: g_gates fp32 [4096 x 1024].
__global__ void __launch_bounds__(256, 1)
hh_mma(const __nv_bfloat16* __restrict__ ahp, const __nv_bfloat16* __restrict__ alp) {
    extern __shared__ __align__(128) char sm[];
    const int tid = threadIdx.x;
    const int wid = tid >> 5, lane = tid & 31;
    const int m0 = blockIdx.x * 128;
    const int n0 = blockIdx.y * 128;
    const int wm = (wid >> 2) * 64;
    const int wn = (wid & 3) * 32;
    const uint32_t smu = smem_to_u32(sm);
    const size_t lda = (size_t)SS * HH;   // 32768

    const __nv_bfloat16* src0 = ahp + (size_t)m0 * lda;
    const __nv_bfloat16* src1 = alp + (size_t)m0 * lda;
    const __nv_bfloat16* src2 = g_whhh + (size_t)n0 * HH;
    const __nv_bfloat16* src3 = g_whhl + (size_t)n0 * HH;

    float acc[4][4][4];
    #pragma unroll
    for (int i = 0; i < 4; i++)
        #pragma unroll
        for (int j = 0; j < 4; j++)
            #pragma unroll
            for (int f = 0; f < 4; f++) acc[i][j][f] = 0.f;

    float4 stg[4][2];
    const int r0 = tid >> 2, g0 = tid & 3;
    const int r1 = (tid + 256) >> 2;

    auto ldg = [&](int k0) {
        stg[0][0] = *(const float4*)(src0 + (size_t)r0 * lda + k0 + g0 * 8);
        stg[0][1] = *(const float4*)(src0 + (size_t)r1 * lda + k0 + g0 * 8);
        stg[1][0] = *(const float4*)(src1 + (size_t)r0 * lda + k0 + g0 * 8);
        stg[1][1] = *(const float4*)(src1 + (size_t)r1 * lda + k0 + g0 * 8);
        stg[2][0] = *(const float4*)(src2 + (size_t)r0 * HH + k0 + g0 * 8);
        stg[2][1] = *(const float4*)(src2 + (size_t)r1 * HH + k0 + g0 * 8);
        stg[3][0] = *(const float4*)(src3 + (size_t)r0 * HH + k0 + g0 * 8);
        stg[3][1] = *(const float4*)(src3 + (size_t)r1 * HH + k0 + g0 * 8);
    };
    auto sts = [&](int stage) {
        char* base = sm + stage * STAGE_B;
        #pragma unroll
        for (int t = 0; t < 4; t++) {
            *(float4*)(base + t * TILE_B + r0 * 80 + g0 * 16) = stg[t][0];
            *(float4*)(base + t * TILE_B + r1 * 80 + g0 * 16) = stg[t][1];
        }
    };
    auto compute = [&](int stage) {
        const uint32_t sAh = smu + stage * STAGE_B;
        const uint32_t sAl = sAh + TILE_B;
        const uint32_t sBh = sAh + 2 * TILE_B;
        const uint32_t sBl = sAh + 3 * TILE_B;
        #pragma unroll
        for (int ks = 0; ks < 2; ks++) {
            const int kb = ks * 32;
            uint32_t bh[4][2], bl[4][2];
            const uint32_t boff = (uint32_t)(wn + (lane & 7)) * 80 + kb + ((lane >> 3) & 1) * 16;
            #pragma unroll
            for (int ni = 0; ni < 4; ni++) {
                ldsm_x2(bh[ni], sBh + boff + ni * 8 * 80);
                ldsm_x2(bl[ni], sBl + boff + ni * 8 * 80);
            }
            const uint32_t aoff = (uint32_t)(wm + (lane & 15)) * 80 + kb + (lane >> 4) * 16;
            #pragma unroll
            for (int mi = 0; mi < 4; mi++) {
                uint32_t ah[4], al[4];
                ldsm_x4(ah, sAh + aoff + mi * 16 * 80);
                ldsm_x4(al, sAl + aoff + mi * 16 * 80);
                #pragma unroll
                for (int ni = 0; ni < 4; ni++) {
                    mma16816(acc[mi][ni], ah, bh[ni]);
                    mma16816(acc[mi][ni], ah, bl[ni]);
                    mma16816(acc[mi][ni], al, bh[ni]);
                }
            }
        }
    };

    ldg(0); sts(0);
    __syncthreads();
    int cur = 0;
    #pragma unroll 1
    for (int k0 = 0; k0 < HH; k0 += 32) {
        bool more = (k0 + 32 < HH);
        if (more) ldg(k0 + 32);
        compute(cur);
        if (more) sts(cur ^ 1);
        __syncthreads();
        cur ^= 1;
    }

    const int gid = lane >> 2, tig = lane & 3;
    #pragma unroll
    for (int mi = 0; mi < 4; mi++) {
        int row0 = m0 + wm + mi * 16 + gid;
        #pragma unroll
        for (int ni = 0; ni < 4; ni++) {
            int col = n0 + wn + ni * 8 + tig * 2;
            float2 v0; v0.x = acc[mi][ni][0]; v0.y = acc[mi][ni][1];
            float2 v1; v1.x = acc[mi][ni][2]; v1.y = acc[mi][ni][3];
            *(float2*)(g_gates + (size_t)row0 * H4 + col) = v0;
            *(float2*)(g_gates + (size_t)(row0 + 8) * H4 + col) = v1;
        }
    }
}

// ============ double-buffered fp32 GEMM: C = A@B^T (+bias1+bias2) (R3-verbatim) ============
__global__ void __launch_bounds__(256, 2)
gemm_abt_db(const float* __restrict__ A, int lda,
            const float* __restrict__ B, int ldb, int K,
            const float* __restrict__ bias1, const float* __restrict__ bias2, int relu,
            float* __restrict__ C, int ldc, int kza, long long czc) {
    A += (size_t)blockIdx.z * kza;
    B += (size_t)blockIdx.z * kza;
    C += (size_t)blockIdx.z * czc;
    __shared__ __align__(16) float As[2][16][128];
    __shared__ __align__(16) float Bs[2][16][128];
    const int tid = threadIdx.x;
    const int tx = tid & 15;
    const int ty = tid >> 4;
    const int m0 = blockIdx.y * 128;
    const int n0 = blockIdx.x * 128;

    float acc[8][8];
    #pragma unroll
    for (int i = 0; i < 8; i++)
        #pragma unroll
        for (int j = 0; j < 8; j++) acc[i][j] = 0.f;

    float4 ra[2], rb[2];
    auto ld = [&](int k0) {
        #pragma unroll
        for (int u = 0; u < 2; ++u) {
            int i = (tid + u * 256) << 2;
            int r = i >> 4, cc = i & 15;
            ra[u] = *(const float4*)(A + (size_t)(m0 + r) * lda + k0 + cc);
            rb[u] = *(const float4*)(B + (size_t)(n0 + r) * ldb + k0 + cc);
        }
    };
    auto st = [&](int buf) {
        #pragma unroll
        for (int u = 0; u < 2; ++u) {
            int i = (tid + u * 256) << 2;
            int r = i >> 4, cc = i & 15;
            As[buf][cc][r] = ra[u].x; As[buf][cc + 1][r] = ra[u].y;
            As[buf][cc + 2][r] = ra[u].z; As[buf][cc + 3][r] = ra[u].w;
            Bs[buf][cc][r] = rb[u].x; Bs[buf][cc + 1][r] = rb[u].y;
            Bs[buf][cc + 2][r] = rb[u].z; Bs[buf][cc + 3][r] = rb[u].w;
        }
    };

    ld(0); st(0);
    __syncthreads();
    int cur = 0;
    #pragma unroll 1
    for (int k0 = 0; k0 < K; k0 += 16) {
        bool more = (k0 + 16 < K);
        if (more) ld(k0 + 16);
        #pragma unroll
        for (int kk = 0; kk < 16; ++kk) {
            float a[8], b[8];
            *(float4*)(a) = *(const float4*)&As[cur][kk][ty * 8];
            *(float4*)(a + 4) = *(const float4*)&As[cur][kk][ty * 8 + 4];
            *(float4*)(b) = *(const float4*)&Bs[cur][kk][tx * 8];
            *(float4*)(b + 4) = *(const float4*)&Bs[cur][kk][tx * 8 + 4];
            #pragma unroll
            for (int i = 0; i < 8; i++)
                #pragma unroll
                for (int j = 0; j < 8; j++)
                    acc[i][j] = fmaf(a[i], b[j], acc[i][j]);
        }
        if (more) st(cur ^ 1);
        __syncthreads();
        cur ^= 1;
    }
    #pragma unroll
    for (int i = 0; i < 8; i++) {
        int m = m0 + ty * 8 + i;
        #pragma unroll
        for (int j = 0; j < 8; j++) {
            int n = n0 + tx * 8 + j;
            float v = acc[i][j];
            if (bias1) v += bias1[n];
            if (bias2) v += bias2[n];
            if (relu) v = fmaxf(v, 0.f);
            C[(size_t)m * ldc + n] = v;
        }
    }
}

// ---------------- LSTM elementwise cell (R3 math + bf16 hi/lo h emit) ----------------
__device__ __forceinline__ float sigf(float x) { return 1.f / (1.f + expf(-x)); }

__global__ void lstm_cell2(int s) {
    int idx = blockIdx.x * blockDim.x + threadIdx.x;  // over B*H
    int b = idx >> 8;
    int h = idx & 255;
    const float* gx = g_gx + ((size_t)b * SS + s) * H4;
    float gi = gx[h];
    float gf = gx[HH + h];
    float gg = gx[2 * HH + h];
    float go = gx[3 * HH + h];
    if (s > 0) {
        const float* gt = g_gates + (size_t)b * H4;
        gi += gt[h];
        gf += gt[HH + h];
        gg += gt[2 * HH + h];
        go += gt[3 * HH + h];
    }
    float ig = sigf(gi);
    float fg = sigf(gf);
    float gv = tanhf(gg);
    float og = sigf(go);
    float cp = (s == 0) ? 0.f : g_c[idx];
    float cn = fmaf(fg, cp, ig * gv);
    g_c[idx] = cn;
    float hv = og * tanhf(cn);
    size_t hidx = ((size_t)b * SS + s) * HH + h;
    g_hs[hidx] = hv;
    __nv_bfloat16 hhi = __float2bfloat16(hv);
    g_hsbh[hidx] = hhi;
    g_hsbl[hidx] = __float2bfloat16(hv - __bfloat162float(hhi));
}

// ---------------- attention: reduce split-K partials, relu, softmax ----------------
__global__ void attn_reduce_softmax(const float* __restrict__ b_ta) {
    int b = blockIdx.x;
    int t = threadIdx.x;  // 128
    __shared__ float sh[4];
    float v = 0.f;
    #pragma unroll
    for (int z = 0; z < KSPLIT; z++) v += g_pattn[((size_t)z * BB + b) * SS + t];
    v = fmaxf(v + b_ta[t], 0.f);
    float m = v;
    #pragma unroll
    for (int o = 16; o > 0; o >>= 1) m = fmaxf(m, __shfl_xor_sync(0xffffffffu, m, o));
    if ((t & 31) == 0) sh[t >> 5] = m;
    __syncthreads();
    float m4 = fmaxf(fmaxf(sh[0], sh[1]), fmaxf(sh[2], sh[3]));
    float e = expf(v - m4);
    float ssum = e;
    #pragma unroll
    for (int o = 16; o > 0; o >>= 1) ssum += __shfl_xor_sync(0xffffffffu, ssum, o);
    __syncthreads();
    if ((t & 31) == 0) sh[t >> 5] = ssum;
    __syncthreads();
    float tot = sh[0] + sh[1] + sh[2] + sh[3];
    g_beta[(size_t)b * SS + t] = e / tot;
}

// ---------------- pooled = sum_s beta*hs ; out = pooled @ W_out^T (R3) ----------------
__global__ void pool_out(const float* __restrict__ W_out, float* __restrict__ out) {
    int b = blockIdx.x;
    int t = threadIdx.x;  // 256, t == h
    __shared__ float sb[SS];
    __shared__ float red[8];
    if (t < SS) sb[t] = g_beta[(size_t)b * SS + t];
    __syncthreads();
    const float* hrow = g_hs + (size_t)b * SS * HH + t;
    float acc = 0.f;
    #pragma unroll 4
    for (int s = 0; s < SS; s++) acc = fmaf(hrow[(size_t)s * HH], sb[s], acc);
    float v = acc * W_out[t];
    #pragma unroll
    for (int o = 16; o > 0; o >>= 1) v += __shfl_xor_sync(0xffffffffu, v, o);
    if ((t & 31) == 0) red[t >> 5] = v;
    __syncthreads();
    if (t == 0) {
        float r = 0.f;
        #pragma unroll
        for (int w = 0; w < 8; w++) r += red[w];
        out[b] = r;
    }
}

// ---------------- launch ----------------
extern "C" void kernel_launch(void* const* d_in, const int* in_sizes, int n_in,
                              void* d_out, int out_size) {
    const float* x     = (const float*)d_in[0];
    const float* gamma = (const float*)d_in[1];
    const float* beta  = (const float*)d_in[2];
    const float* W_in  = (const float*)d_in[3];
    const float* W_ih  = (const float*)d_in[4];
    const float* b_ih  = (const float*)d_in[5];
    const float* W_hh  = (const float*)d_in[6];
    const float* b_hh  = (const float*)d_in[7];
    const float* W_ta  = (const float*)d_in[8];
    const float* b_ta  = (const float*)d_in[9];
    const float* W_out = (const float*)d_in[10];
    float* out = (float*)d_out;

    float *p_proj, *p_gx, *p_hs, *p_pattn;
    __nv_bfloat16 *p_hsbh, *p_hsbl, *p_wh, *p_wl, *p_whhh, *p_whhl;
    cudaGetSymbolAddress((void**)&p_proj, g_proj);
    cudaGetSymbolAddress((void**)&p_gx, g_gx);
    cudaGetSymbolAddress((void**)&p_hs, g_hs);
    cudaGetSymbolAddress((void**)&p_pattn, g_pattn);
    cudaGetSymbolAddress((void**)&p_hsbh, g_hsbh);
    cudaGetSymbolAddress((void**)&p_hsbl, g_hsbl);
    cudaGetSymbolAddress((void**)&p_wh, g_wh);
    cudaGetSymbolAddress((void**)&p_wl, g_wl);
    cudaGetSymbolAddress((void**)&p_whhh, g_whhh);
    cudaGetSymbolAddress((void**)&p_whhl, g_whhl);

    cudaFuncSetAttribute(proj_mma, cudaFuncAttributeMaxDynamicSharedMemorySize, SMEM_MMA);
    cudaFuncSetAttribute(hh_mma, cudaFuncAttributeMaxDynamicSharedMemorySize, SMEM_MMA);

    // BatchNorm + splits
    bn_stats<<<INF / 256, 256>>>(x, gamma, beta);
    bn_apply_split<<<(BB * INF / 4) / 256, 256>>>(x);
    cvt_split<<<((size_t)INF * INF / 4) / 256, 256>>>(W_in, p_wh, p_wl);
    cvt_split<<<((size_t)H4 * HH / 4) / 256, 256>>>(W_hh, p_whhh, p_whhl);

    // proj = xn @ W_in^T (fp32 out, R3 path)
    proj_mma<<<dim3(BB / 128, INF / 128), 256, SMEM_MMA>>>(p_proj);

    // gx = proj2d @ W_ih^T + b_ih + b_hh   [B*S, 1024], K=64 (R3 path)
    gemm_abt_db<<<dim3(H4 / 128, (BB * SS) / 128, 1), 256>>>(
        p_proj, DD, W_ih, DD, DD, b_ih, b_hh, 0, p_gx, H4, 0, 0);

    // LSTM scan: bf16x3 MMA for h@W_hh^T (s>=1) + elementwise cell
    lstm_cell2<<<BB * HH / 256, 256>>>(0);
    for (int s = 1; s < SS; s++) {
        hh_mma<<<dim3(BB / 128, H4 / 128), 256, SMEM_MMA>>>(
            p_hsbh + (size_t)(s - 1) * HH, p_hsbl + (size_t)(s - 1) * HH);
        lstm_cell2<<<BB * HH / 256, 256>>>(s);
    }

    // attention: split-K fp32 partials (R3 path) then fused reduce+relu+softmax
    gemm_abt_db<<<dim3(1, BB / 128, KSPLIT), 256>>>(
        p_hs, SS * HH, W_ta, SS * HH, KCH, nullptr, nullptr, 0,
        p_pattn, SS, KCH, (long long)BB * SS);
    attn_reduce_softmax<<<BB, SS>>>(b_ta);
    pool_out<<<BB, HH>>>(W_out, out);
}

// round 7
// speedup vs baseline: 2.9065x; 1.2297x over previous
#include <cuda_runtime.h>
#include <cuda_bf16.h>
#include <math.h>
#include <stdint.h>

#define BB 4096
#define SS 128
#define DD 64
#define HH 256
#define INF 8192
#define H4 1024
#define KSPLIT 8

// ---------------- scratch (device globals; zero-init at load) ----------------
__device__ float g_scale[INF];
__device__ float g_shift[INF];
__device__ __nv_bfloat16 g_xnh[(size_t)BB * INF];        // 64 MB
__device__ __nv_bfloat16 g_xnl[(size_t)BB * INF];        // 64 MB
__device__ __nv_bfloat16 g_wh[(size_t)INF * INF];        // 128 MB
__device__ __nv_bfloat16 g_wl[(size_t)INF * INF];        // 128 MB
__device__ __nv_bfloat16 g_pjh[(size_t)BB * INF];        // 64 MB (proj hi)
__device__ __nv_bfloat16 g_pjl[(size_t)BB * INF];        // 64 MB (proj lo)
__device__ __nv_bfloat16 g_whhh[(size_t)H4 * HH];        // W_hh hi
__device__ __nv_bfloat16 g_whhl[(size_t)H4 * HH];        // W_hh lo
__device__ __nv_bfloat16 g_wihh[(size_t)H4 * DD];        // W_ih hi
__device__ __nv_bfloat16 g_wihl[(size_t)H4 * DD];        // W_ih lo
__device__ __nv_bfloat16 g_wtah[(size_t)SS * SS * HH];   // 8 MB
__device__ __nv_bfloat16 g_wtal[(size_t)SS * SS * HH];   // 8 MB
__device__ float g_gates[(size_t)BB * H4];               // 16 MB
__device__ float g_c[(size_t)BB * HH];                   // 4 MB
__device__ __nv_bfloat16 g_hsbh[(size_t)BB * SS * HH];   // 256 MB (hs hi)
__device__ __nv_bfloat16 g_hsbl[(size_t)BB * SS * HH];   // 256 MB (hs lo)
__device__ float g_pattn[(size_t)KSPLIT * BB * SS];      // 16 MB
__device__ float g_beta[(size_t)BB * SS];                // 2 MB

// ============================ PTX helpers (family-wide) ============================
__device__ __forceinline__ uint32_t smem_to_u32(const void* p) {
    uint32_t a;
    asm("{ .reg .u64 t; cvta.to.shared.u64 t, %1; cvt.u32.u64 %0, t; }" : "=r"(a) : "l"(p));
    return a;
}
__device__ __forceinline__ void ldsm_x4(uint32_t* r, uint32_t a) {
    asm volatile("ldmatrix.sync.aligned.m8n8.x4.shared.b16 {%0,%1,%2,%3}, [%4];"
                 : "=r"(r[0]), "=r"(r[1]), "=r"(r[2]), "=r"(r[3]) : "r"(a));
}
__device__ __forceinline__ void ldsm_x2(uint32_t* r, uint32_t a) {
    asm volatile("ldmatrix.sync.aligned.m8n8.x2.shared.b16 {%0,%1}, [%2];"
                 : "=r"(r[0]), "=r"(r[1]) : "r"(a));
}
__device__ __forceinline__ void mma16816(float* c, const uint32_t* a, const uint32_t* b) {
    asm volatile(
        "mma.sync.aligned.m16n8k16.row.col.f32.bf16.bf16.f32 "
        "{%0,%1,%2,%3}, {%4,%5,%6,%7}, {%8,%9}, {%0,%1,%2,%3};"
        : "+f"(c[0]), "+f"(c[1]), "+f"(c[2]), "+f"(c[3])
        : "r"(a[0]), "r"(a[1]), "r"(a[2]), "r"(a[3]), "r"(b[0]), "r"(b[1]));
}

// smem tiling: 4 tiles (Ah, Al, Bh, Bl), 128 rows x 32 bf16 padded to 80 B/row.
#define TILE_B (128 * 80)        // 10240 B
#define STAGE_B (4 * TILE_B)     // 40960 B
#define SMEM_MMA (2 * STAGE_B)   // 81920 B

// ---------------- BatchNorm stats -> scale/shift ----------------
__global__ void bn_stats(const float* __restrict__ x,
                         const float* __restrict__ gamma,
                         const float* __restrict__ beta) {
    int k = blockIdx.x * blockDim.x + threadIdx.x;
    float s = 0.f, s2 = 0.f;
    #pragma unroll 8
    for (int b = 0; b < BB; b++) {
        float v = x[(size_t)b * INF + k];
        s += v; s2 += v * v;
    }
    float mean = s * (1.f / BB);
    float var = s2 * (1.f / BB) - mean * mean;
    float sc = gamma[k] * rsqrtf(var + 1e-5f);
    g_scale[k] = sc;
    g_shift[k] = beta[k] - mean * sc;
}

// BN apply fused with bf16 hi/lo split
__global__ void bn_apply_split(const float* __restrict__ x) {
    size_t i = (size_t)blockIdx.x * blockDim.x + threadIdx.x;  // float4 index
    float4 v = ((const float4*)x)[i];
    int k = (int)((i * 4) & (INF - 1));
    float o0 = fmaf(v.x, g_scale[k + 0], g_shift[k + 0]);
    float o1 = fmaf(v.y, g_scale[k + 1], g_shift[k + 1]);
    float o2 = fmaf(v.z, g_scale[k + 2], g_shift[k + 2]);
    float o3 = fmaf(v.w, g_scale[k + 3], g_shift[k + 3]);
    __nv_bfloat16 h0 = __float2bfloat16(o0), h1 = __float2bfloat16(o1);
    __nv_bfloat16 h2 = __float2bfloat16(o2), h3 = __float2bfloat16(o3);
    __nv_bfloat162 ph0; ph0.x = h0; ph0.y = h1;
    __nv_bfloat162 ph1; ph1.x = h2; ph1.y = h3;
    *(__nv_bfloat162*)(g_xnh + i * 4) = ph0;
    *(__nv_bfloat162*)(g_xnh + i * 4 + 2) = ph1;
    __nv_bfloat162 pl0, pl1;
    pl0.x = __float2bfloat16(o0 - __bfloat162float(h0));
    pl0.y = __float2bfloat16(o1 - __bfloat162float(h1));
    pl1.x = __float2bfloat16(o2 - __bfloat162float(h2));
    pl1.y = __float2bfloat16(o3 - __bfloat162float(h3));
    *(__nv_bfloat162*)(g_xnl + i * 4) = pl0;
    *(__nv_bfloat162*)(g_xnl + i * 4 + 2) = pl1;
}

// generic fp32 -> bf16 hi/lo split
__global__ void cvt_split(const float* __restrict__ src,
                          __nv_bfloat16* __restrict__ dh,
                          __nv_bfloat16* __restrict__ dl) {
    size_t i = (size_t)blockIdx.x * blockDim.x + threadIdx.x;  // float4 index
    float4 v = ((const float4*)src)[i];
    __nv_bfloat16 h0 = __float2bfloat16(v.x), h1 = __float2bfloat16(v.y);
    __nv_bfloat16 h2 = __float2bfloat16(v.z), h3 = __float2bfloat16(v.w);
    __nv_bfloat162 ph0; ph0.x = h0; ph0.y = h1;
    __nv_bfloat162 ph1; ph1.x = h2; ph1.y = h3;
    *(__nv_bfloat162*)(dh + i * 4) = ph0;
    *(__nv_bfloat162*)(dh + i * 4 + 2) = ph1;
    __nv_bfloat162 pl0, pl1;
    pl0.x = __float2bfloat16(v.x - __bfloat162float(h0));
    pl0.y = __float2bfloat16(v.y - __bfloat162float(h1));
    pl1.x = __float2bfloat16(v.z - __bfloat162float(h2));
    pl1.y = __float2bfloat16(v.w - __bfloat162float(h3));
    *(__nv_bfloat162*)(dl + i * 4) = pl0;
    *(__nv_bfloat162*)(dl + i * 4 + 2) = pl1;
}

// ============ proj = xn @ W_in^T via mma.sync bf16x3 -> bf16 hi/lo out ============
__global__ void __launch_bounds__(256, 1)
proj_mma() {
    extern __shared__ __align__(128) char sm[];
    const int tid = threadIdx.x;
    const int wid = tid >> 5, lane = tid & 31;
    const int m0 = blockIdx.x * 128;
    const int n0 = blockIdx.y * 128;
    const int wm = (wid >> 2) * 64;
    const int wn = (wid & 3) * 32;
    const uint32_t smu = smem_to_u32(sm);

    const __nv_bfloat16* src0 = g_xnh + (size_t)m0 * INF;
    const __nv_bfloat16* src1 = g_xnl + (size_t)m0 * INF;
    const __nv_bfloat16* src2 = g_wh + (size_t)n0 * INF;
    const __nv_bfloat16* src3 = g_wl + (size_t)n0 * INF;

    float acc[4][4][4];
    #pragma unroll
    for (int i = 0; i < 4; i++)
        #pragma unroll
        for (int j = 0; j < 4; j++)
            #pragma unroll
            for (int f = 0; f < 4; f++) acc[i][j][f] = 0.f;

    float4 stg[4][2];
    const int r0 = tid >> 2, g0 = tid & 3;
    const int r1 = (tid + 256) >> 2;

    auto ldg = [&](int k0) {
        const __nv_bfloat16* s[4] = {src0, src1, src2, src3};
        #pragma unroll
        for (int t = 0; t < 4; t++) {
            stg[t][0] = *(const float4*)(s[t] + (size_t)r0 * INF + k0 + g0 * 8);
            stg[t][1] = *(const float4*)(s[t] + (size_t)r1 * INF + k0 + g0 * 8);
        }
    };
    auto sts = [&](int stage) {
        char* base = sm + stage * STAGE_B;
        #pragma unroll
        for (int t = 0; t < 4; t++) {
            *(float4*)(base + t * TILE_B + r0 * 80 + g0 * 16) = stg[t][0];
            *(float4*)(base + t * TILE_B + r1 * 80 + g0 * 16) = stg[t][1];
        }
    };
    auto compute = [&](int stage) {
        const uint32_t sAh = smu + stage * STAGE_B;
        const uint32_t sAl = sAh + TILE_B;
        const uint32_t sBh = sAh + 2 * TILE_B;
        const uint32_t sBl = sAh + 3 * TILE_B;
        #pragma unroll
        for (int ks = 0; ks < 2; ks++) {
            const int kb = ks * 32;
            uint32_t bh[4][2], bl[4][2];
            const uint32_t boff = (uint32_t)(wn + (lane & 7)) * 80 + kb + ((lane >> 3) & 1) * 16;
            #pragma unroll
            for (int ni = 0; ni < 4; ni++) {
                ldsm_x2(bh[ni], sBh + boff + ni * 8 * 80);
                ldsm_x2(bl[ni], sBl + boff + ni * 8 * 80);
            }
            const uint32_t aoff = (uint32_t)(wm + (lane & 15)) * 80 + kb + (lane >> 4) * 16;
            #pragma unroll
            for (int mi = 0; mi < 4; mi++) {
                uint32_t ah[4], al[4];
                ldsm_x4(ah, sAh + aoff + mi * 16 * 80);
                ldsm_x4(al, sAl + aoff + mi * 16 * 80);
                #pragma unroll
                for (int ni = 0; ni < 4; ni++) {
                    mma16816(acc[mi][ni], ah, bh[ni]);
                    mma16816(acc[mi][ni], ah, bl[ni]);
                    mma16816(acc[mi][ni], al, bh[ni]);
                }
            }
        }
    };

    ldg(0); sts(0);
    __syncthreads();
    int cur = 0;
    #pragma unroll 1
    for (int k0 = 0; k0 < INF; k0 += 32) {
        bool more = (k0 + 32 < INF);
        if (more) ldg(k0 + 32);
        compute(cur);
        if (more) sts(cur ^ 1);
        __syncthreads();
        cur ^= 1;
    }

    const int gid = lane >> 2, tig = lane & 3;
    #pragma unroll
    for (int mi = 0; mi < 4; mi++) {
        int row0 = m0 + wm + mi * 16 + gid;
        #pragma unroll
        for (int ni = 0; ni < 4; ni++) {
            int col = n0 + wn + ni * 8 + tig * 2;
            const float* a = acc[mi][ni];
            #pragma unroll
            for (int half = 0; half < 2; half++) {
                int row = row0 + half * 8;
                float c0 = a[half * 2 + 0], c1 = a[half * 2 + 1];
                __nv_bfloat162 hp, lp;
                hp.x = __float2bfloat16(c0); hp.y = __float2bfloat16(c1);
                lp.x = __float2bfloat16(c0 - __bfloat162float(hp.x));
                lp.y = __float2bfloat16(c1 - __bfloat162float(hp.y));
                *(__nv_bfloat162*)(g_pjh + (size_t)row * INF + col) = hp;
                *(__nv_bfloat162*)(g_pjl + (size_t)row * INF + col) = lp;
            }
        }
    }
}

// ===== gates_mma: g_gates = h_{s-1}@W_hh^T + xs_s@W_ih^T (two-segment bf16x3) =====
// Unpermuted weights, validated hh_mma skeleton + float2 epilogue. s==0 skips hh.
__global__ void __launch_bounds__(256, 1)
gates_mma(int s) {
    extern __shared__ __align__(128) char sm[];
    const int tid = threadIdx.x;
    const int wid = tid >> 5, lane = tid & 31;
    const int m0 = blockIdx.x * 128;
    const int n0 = blockIdx.y * 128;
    const int wm = (wid >> 2) * 64;
    const int wn = (wid & 3) * 32;
    const uint32_t smu = smem_to_u32(sm);

    const int c0 = (s == 0) ? 8 : 0;   // s==0: h_{-1}==0 -> hh segment skipped
    const __nv_bfloat16* a1h = g_hsbh + (size_t)(s - 1) * HH;  // deref'd only if s>0
    const __nv_bfloat16* a1l = g_hsbl + (size_t)(s - 1) * HH;
    const size_t ld1 = (size_t)SS * HH;
    const __nv_bfloat16* a2h = g_pjh + (size_t)s * DD;
    const __nv_bfloat16* a2l = g_pjl + (size_t)s * DD;

    float acc[4][4][4];
    #pragma unroll
    for (int i = 0; i < 4; i++)
        #pragma unroll
        for (int j = 0; j < 4; j++)
            #pragma unroll
            for (int f = 0; f < 4; f++) acc[i][j][f] = 0.f;

    float4 stg[4][2];
    const int r0 = tid >> 2, g0 = tid & 3;
    const int r1 = (tid + 256) >> 2;

    // chunk c: 0..7 -> hh segment (K=256), 8..9 -> ih segment (K=64)
    auto ldg = [&](int c) {
        const __nv_bfloat16 *pah, *pal, *pbh, *pbl;
        size_t la; int lb, k0;
        if (c < 8) { k0 = c * 32; pah = a1h; pal = a1l; la = ld1;
                     pbh = g_whhh; pbl = g_whhl; lb = HH; }
        else       { k0 = (c - 8) * 32; pah = a2h; pal = a2l; la = INF;
                     pbh = g_wihh; pbl = g_wihl; lb = DD; }
        stg[0][0] = *(const float4*)(pah + (size_t)(m0 + r0) * la + k0 + g0 * 8);
        stg[0][1] = *(const float4*)(pah + (size_t)(m0 + r1) * la + k0 + g0 * 8);
        stg[1][0] = *(const float4*)(pal + (size_t)(m0 + r0) * la + k0 + g0 * 8);
        stg[1][1] = *(const float4*)(pal + (size_t)(m0 + r1) * la + k0 + g0 * 8);
        stg[2][0] = *(const float4*)(pbh + (size_t)(n0 + r0) * lb + k0 + g0 * 8);
        stg[2][1] = *(const float4*)(pbh + (size_t)(n0 + r1) * lb + k0 + g0 * 8);
        stg[3][0] = *(const float4*)(pbl + (size_t)(n0 + r0) * lb + k0 + g0 * 8);
        stg[3][1] = *(const float4*)(pbl + (size_t)(n0 + r1) * lb + k0 + g0 * 8);
    };
    auto sts = [&](int stage) {
        char* base = sm + stage * STAGE_B;
        #pragma unroll
        for (int t = 0; t < 4; t++) {
            *(float4*)(base + t * TILE_B + r0 * 80 + g0 * 16) = stg[t][0];
            *(float4*)(base + t * TILE_B + r1 * 80 + g0 * 16) = stg[t][1];
        }
    };
    auto compute = [&](int stage) {
        const uint32_t sAh = smu + stage * STAGE_B;
        const uint32_t sAl = sAh + TILE_B;
        const uint32_t sBh = sAh + 2 * TILE_B;
        const uint32_t sBl = sAh + 3 * TILE_B;
        #pragma unroll
        for (int ks = 0; ks < 2; ks++) {
            const int kb = ks * 32;
            uint32_t bh[4][2], bl[4][2];
            const uint32_t boff = (uint32_t)(wn + (lane & 7)) * 80 + kb + ((lane >> 3) & 1) * 16;
            #pragma unroll
            for (int ni = 0; ni < 4; ni++) {
                ldsm_x2(bh[ni], sBh + boff + ni * 8 * 80);
                ldsm_x2(bl[ni], sBl + boff + ni * 8 * 80);
            }
            const uint32_t aoff = (uint32_t)(wm + (lane & 15)) * 80 + kb + (lane >> 4) * 16;
            #pragma unroll
            for (int mi = 0; mi < 4; mi++) {
                uint32_t ah[4], al[4];
                ldsm_x4(ah, sAh + aoff + mi * 16 * 80);
                ldsm_x4(al, sAl + aoff + mi * 16 * 80);
                #pragma unroll
                for (int ni = 0; ni < 4; ni++) {
                    mma16816(acc[mi][ni], ah, bh[ni]);
                    mma16816(acc[mi][ni], ah, bl[ni]);
                    mma16816(acc[mi][ni], al, bh[ni]);
                }
            }
        }
    };

    ldg(c0); sts(0);
    __syncthreads();
    int cur = 0;
    #pragma unroll 1
    for (int c = c0; c < 10; ++c) {
        bool more = (c < 9);
        if (more) ldg(c + 1);
        compute(cur);
        if (more) sts(cur ^ 1);
        __syncthreads();
        cur ^= 1;
    }

    const int gid = lane >> 2, tig = lane & 3;
    #pragma unroll
    for (int mi = 0; mi < 4; mi++) {
        int row0 = m0 + wm + mi * 16 + gid;
        #pragma unroll
        for (int ni = 0; ni < 4; ni++) {
            int col = n0 + wn + ni * 8 + tig * 2;
            float2 v0; v0.x = acc[mi][ni][0]; v0.y = acc[mi][ni][1];
            float2 v1; v1.x = acc[mi][ni][2]; v1.y = acc[mi][ni][3];
            *(float2*)(g_gates + (size_t)row0 * H4 + col) = v0;
            *(float2*)(g_gates + (size_t)(row0 + 8) * H4 + col) = v1;
        }
    }
}

// ---------------- LSTM elementwise cell (bias added here; bf16 hi/lo h emit) ----------------
__device__ __forceinline__ float sigf(float x) { return 1.f / (1.f + expf(-x)); }

__global__ void lstm_cell2(const float* __restrict__ b_ih, const float* __restrict__ b_hh,
                           int s) {
    int idx = blockIdx.x * blockDim.x + threadIdx.x;  // over B*H
    int b = idx >> 8;
    int h = idx & 255;
    const float* gt = g_gates + (size_t)b * H4;
    float gi = gt[h]          + b_ih[h]          + b_hh[h];
    float gf = gt[HH + h]     + b_ih[HH + h]     + b_hh[HH + h];
    float gg = gt[2 * HH + h] + b_ih[2 * HH + h] + b_hh[2 * HH + h];
    float go = gt[3 * HH + h] + b_ih[3 * HH + h] + b_hh[3 * HH + h];
    float ig = sigf(gi);
    float fg = sigf(gf);
    float gv = tanhf(gg);
    float og = sigf(go);
    float cp = (s == 0) ? 0.f : g_c[idx];
    float cn = fmaf(fg, cp, ig * gv);
    g_c[idx] = cn;
    float hv = og * tanhf(cn);
    size_t hidx = ((size_t)b * SS + s) * HH + h;
    __nv_bfloat16 hhi = __float2bfloat16(hv);
    g_hsbh[hidx] = hhi;
    g_hsbl[hidx] = __float2bfloat16(hv - __bfloat162float(hhi));
}

// ============ attention logits: split-K bf16x3 MMA -> fp32 partials ============
__global__ void __launch_bounds__(256, 1)
attn_mma() {
    extern __shared__ __align__(128) char sm[];
    const int tid = threadIdx.x;
    const int wid = tid >> 5, lane = tid & 31;
    const int m0 = blockIdx.y * 128;
    const int z = blockIdx.z;
    const int wm = (wid >> 2) * 64;
    const int wn = (wid & 3) * 32;
    const uint32_t smu = smem_to_u32(sm);
    const size_t ldk = (size_t)SS * HH;   // 32768

    const __nv_bfloat16* src0 = g_hsbh + (size_t)m0 * ldk + z * 4096;
    const __nv_bfloat16* src1 = g_hsbl + (size_t)m0 * ldk + z * 4096;
    const __nv_bfloat16* src2 = g_wtah + z * 4096;
    const __nv_bfloat16* src3 = g_wtal + z * 4096;

    float acc[4][4][4];
    #pragma unroll
    for (int i = 0; i < 4; i++)
        #pragma unroll
        for (int j = 0; j < 4; j++)
            #pragma unroll
            for (int f = 0; f < 4; f++) acc[i][j][f] = 0.f;

    float4 stg[4][2];
    const int r0 = tid >> 2, g0 = tid & 3;
    const int r1 = (tid + 256) >> 2;

    auto ldg = [&](int k0) {
        stg[0][0] = *(const float4*)(src0 + (size_t)r0 * ldk + k0 + g0 * 8);
        stg[0][1] = *(const float4*)(src0 + (size_t)r1 * ldk + k0 + g0 * 8);
        stg[1][0] = *(const float4*)(src1 + (size_t)r0 * ldk + k0 + g0 * 8);
        stg[1][1] = *(const float4*)(src1 + (size_t)r1 * ldk + k0 + g0 * 8);
        stg[2][0] = *(const float4*)(src2 + (size_t)r0 * ldk + k0 + g0 * 8);
        stg[2][1] = *(const float4*)(src2 + (size_t)r1 * ldk + k0 + g0 * 8);
        stg[3][0] = *(const float4*)(src3 + (size_t)r0 * ldk + k0 + g0 * 8);
        stg[3][1] = *(const float4*)(src3 + (size_t)r1 * ldk + k0 + g0 * 8);
    };
    auto sts = [&](int stage) {
        char* base = sm + stage * STAGE_B;
        #pragma unroll
        for (int t = 0; t < 4; t++) {
            *(float4*)(base + t * TILE_B + r0 * 80 + g0 * 16) = stg[t][0];
            *(float4*)(base + t * TILE_B + r1 * 80 + g0 * 16) = stg[t][1];
        }
    };
    auto compute = [&](int stage) {
        const uint32_t sAh = smu + stage * STAGE_B;
        const uint32_t sAl = sAh + TILE_B;
        const uint32_t sBh = sAh + 2 * TILE_B;
        const uint32_t sBl = sAh + 3 * TILE_B;
        #pragma unroll
        for (int ks = 0; ks < 2; ks++) {
            const int kb = ks * 32;
            uint32_t bh[4][2], bl[4][2];
            const uint32_t boff = (uint32_t)(wn + (lane & 7)) * 80 + kb + ((lane >> 3) & 1) * 16;
            #pragma unroll
            for (int ni = 0; ni < 4; ni++) {
                ldsm_x2(bh[ni], sBh + boff + ni * 8 * 80);
                ldsm_x2(bl[ni], sBl + boff + ni * 8 * 80);
            }
            const uint32_t aoff = (uint32_t)(wm + (lane & 15)) * 80 + kb + (lane >> 4) * 16;
            #pragma unroll
            for (int mi = 0; mi < 4; mi++) {
                uint32_t ah[4], al[4];
                ldsm_x4(ah, sAh + aoff + mi * 16 * 80);
                ldsm_x4(al, sAl + aoff + mi * 16 * 80);
                #pragma unroll
                for (int ni = 0; ni < 4; ni++) {
                    mma16816(acc[mi][ni], ah, bh[ni]);
                    mma16816(acc[mi][ni], ah, bl[ni]);
                    mma16816(acc[mi][ni], al, bh[ni]);
                }
            }
        }
    };

    ldg(0); sts(0);
    __syncthreads();
    int cur = 0;
    #pragma unroll 1
    for (int k0 = 0; k0 < 4096; k0 += 32) {
        bool more = (k0 + 32 < 4096);
        if (more) ldg(k0 + 32);
        compute(cur);
        if (more) sts(cur ^ 1);
        __syncthreads();
        cur ^= 1;
    }

    const int gid = lane >> 2, tig = lane & 3;
    float* outp = g_pattn + (size_t)z * BB * SS;
    #pragma unroll
    for (int mi = 0; mi < 4; mi++) {
        int row0 = m0 + wm + mi * 16 + gid;
        #pragma unroll
        for (int ni = 0; ni < 4; ni++) {
            int col = wn + ni * 8 + tig * 2;
            float2 v0; v0.x = acc[mi][ni][0]; v0.y = acc[mi][ni][1];
            float2 v1; v1.x = acc[mi][ni][2]; v1.y = acc[mi][ni][3];
            *(float2*)(outp + (size_t)row0 * SS + col) = v0;
            *(float2*)(outp + (size_t)(row0 + 8) * SS + col) = v1;
        }
    }
}

// ---------------- attention: reduce split-K partials, relu, softmax ----------------
__global__ void attn_reduce_softmax(const float* __restrict__ b_ta) {
    int b = blockIdx.x;
    int t = threadIdx.x;  // 128
    __shared__ float sh[4];
    float v = 0.f;
    #pragma unroll
    for (int z = 0; z < KSPLIT; z++) v += g_pattn[((size_t)z * BB + b) * SS + t];
    v = fmaxf(v + b_ta[t], 0.f);
    float m = v;
    #pragma unroll
    for (int o = 16; o > 0; o >>= 1) m = fmaxf(m, __shfl_xor_sync(0xffffffffu, m, o));
    if ((t & 31) == 0) sh[t >> 5] = m;
    __syncthreads();
    float m4 = fmaxf(fmaxf(sh[0], sh[1]), fmaxf(sh[2], sh[3]));
    float e = expf(v - m4);
    float ssum = e;
    #pragma unroll
    for (int o = 16; o > 0; o >>= 1) ssum += __shfl_xor_sync(0xffffffffu, ssum, o);
    __syncthreads();
    if ((t & 31) == 0) sh[t >> 5] = ssum;
    __syncthreads();
    float tot = sh[0] + sh[1] + sh[2] + sh[3];
    g_beta[(size_t)b * SS + t] = e / tot;
}

// ---------------- pooled = sum_s beta*hs ; out = pooled @ W_out^T (bf16 hs) ----------------
__global__ void pool_out(const float* __restrict__ W_out, float* __restrict__ out) {
    int b = blockIdx.x;
    int t = threadIdx.x;  // 256, t == h
    __shared__ float sb[SS];
    __shared__ float red[8];
    if (t < SS) sb[t] = g_beta[(size_t)b * SS + t];
    __syncthreads();
    const __nv_bfloat16* hh = g_hsbh + (size_t)b * SS * HH + t;
    const __nv_bfloat16* hl = g_hsbl + (size_t)b * SS * HH + t;
    float acc = 0.f;
    #pragma unroll 4
    for (int s = 0; s < SS; s++) {
        float hv = __bfloat162float(hh[(size_t)s * HH]) + __bfloat162float(hl[(size_t)s * HH]);
        acc = fmaf(hv, sb[s], acc);
    }
    float v = acc * W_out[t];
    #pragma unroll
    for (int o = 16; o > 0; o >>= 1) v += __shfl_xor_sync(0xffffffffu, v, o);
    if ((t & 31) == 0) red[t >> 5] = v;
    __syncthreads();
    if (t == 0) {
        float r = 0.f;
        #pragma unroll
        for (int w = 0; w < 8; w++) r += red[w];
        out[b] = r;
    }
}

// ---------------- launch ----------------
extern "C" void kernel_launch(void* const* d_in, const int* in_sizes, int n_in,
                              void* d_out, int out_size) {
    const float* x     = (const float*)d_in[0];
    const float* gamma = (const float*)d_in[1];
    const float* beta  = (const float*)d_in[2];
    const float* W_in  = (const float*)d_in[3];
    const float* W_ih  = (const float*)d_in[4];
    const float* b_ih  = (const float*)d_in[5];
    const float* W_hh  = (const float*)d_in[6];
    const float* b_hh  = (const float*)d_in[7];
    const float* W_ta  = (const float*)d_in[8];
    const float* b_ta  = (const float*)d_in[9];
    const float* W_out = (const float*)d_in[10];
    float* out = (float*)d_out;

    __nv_bfloat16 *p_wh, *p_wl, *p_whhh, *p_whhl, *p_wihh, *p_wihl, *p_wtah, *p_wtal;
    cudaGetSymbolAddress((void**)&p_wh, g_wh);
    cudaGetSymbolAddress((void**)&p_wl, g_wl);
    cudaGetSymbolAddress((void**)&p_whhh, g_whhh);
    cudaGetSymbolAddress((void**)&p_whhl, g_whhl);
    cudaGetSymbolAddress((void**)&p_wihh, g_wihh);
    cudaGetSymbolAddress((void**)&p_wihl, g_wihl);
    cudaGetSymbolAddress((void**)&p_wtah, g_wtah);
    cudaGetSymbolAddress((void**)&p_wtal, g_wtal);

    cudaFuncSetAttribute(proj_mma, cudaFuncAttributeMaxDynamicSharedMemorySize, SMEM_MMA);
    cudaFuncSetAttribute(gates_mma, cudaFuncAttributeMaxDynamicSharedMemorySize, SMEM_MMA);
    cudaFuncSetAttribute(attn_mma, cudaFuncAttributeMaxDynamicSharedMemorySize, SMEM_MMA);

    // BatchNorm + splits
    bn_stats<<<INF / 256, 256>>>(x, gamma, beta);
    bn_apply_split<<<(BB * INF / 4) / 256, 256>>>(x);
    cvt_split<<<((size_t)INF * INF / 4) / 256, 256>>>(W_in, p_wh, p_wl);
    cvt_split<<<((size_t)H4 * HH / 4) / 256, 256>>>(W_hh, p_whhh, p_whhl);
    cvt_split<<<((size_t)H4 * DD / 4) / 256, 256>>>(W_ih, p_wihh, p_wihl);
    cvt_split<<<((size_t)SS * SS * HH / 4) / 256, 256>>>(W_ta, p_wtah, p_wtal);

    // proj = xn @ W_in^T -> bf16 hi/lo
    proj_mma<<<dim3(BB / 128, INF / 128), 256, SMEM_MMA>>>();

    // LSTM scan: two-segment gates MMA + elementwise cell (bias in cell)
    for (int s = 0; s < SS; s++) {
        gates_mma<<<dim3(BB / 128, H4 / 128), 256, SMEM_MMA>>>(s);
        lstm_cell2<<<BB * HH / 256, 256>>>(b_ih, b_hh, s);
    }

    // attention: split-K bf16 logits, fused reduce+relu+softmax, pool
    attn_mma<<<dim3(1, BB / 128, KSPLIT), 256, SMEM_MMA>>>();
    attn_reduce_softmax<<<BB, SS>>>(b_ta);
    pool_out<<<BB, HH>>>(W_out, out);
}